// round 13
// baseline (speedup 1.0000x reference)
#include <cuda_runtime.h>
#include <math.h>

#define THREADS 128
#define WARPS_PER_BLOCK (THREADS / 32)

// Per-batch partial loss scratch (B = 4096 for this problem; padded for safety).
__device__ float g_partial[8192];
__device__ unsigned int g_count;   // zero at module load; reset by last block each call

__device__ __forceinline__ float huber1(float x) {
    float a = fabsf(x);
    float q = fminf(a, 1.0f);
    return 0.5f * q * q + (a - q);
}

__device__ __forceinline__ float4 ldcs4(const float4* p) {
    return __ldcs(p);
}

__global__ __launch_bounds__(THREADS, 6)   // raise reg budget (~85) so 16-deep load batches stay live
void loss_warp_kernel(
    const float* __restrict__ mask_mean,     // (B,3)
    const float* __restrict__ pc,            // (B,3,N)
    const float* __restrict__ xd,            // (B,3,N)
    const float* __restrict__ center,        // (B,3)
    const float* __restrict__ size_res,      // (B,3)
    const float* __restrict__ head_res,      // (B,)
    const float* __restrict__ mean_sizes,    // (8,3)
    const int*   __restrict__ size_cls,      // (B,)
    const int*   __restrict__ head_cls,      // (B,)
    float* __restrict__ out,
    int Npts, int Bn, int nblocks)
{
    const int t    = threadIdx.x;
    const int lane = t & 31;
    const int wid  = t >> 5;
    const int gw   = blockIdx.x * WARPS_PER_BLOCK + wid;   // global warp id
    const int nwarps = nblocks * WARPS_PER_BLOCK;
    const int n4 = Npts >> 2;          // float4s per row

    // Each warp processes whole batches independently — no block barriers
    // anywhere in the streaming path.
    for (int b = gw; b < Bn; b += nwarps) {
        const size_t base = (size_t)b * 3 * (size_t)Npts;
        const float4* __restrict__ px  = (const float4*)(pc + base);           // x row
        const float4* __restrict__ py  = (const float4*)(pc + base + Npts);    // y row
        const float4* __restrict__ pdl = (const float4*)(xd + base);           // all 3 rows

        float Sx = 0.f, Sy = 0.f, Sxx = 0.f, Syy = 0.f, Sxy = 0.f, Sq = 0.f;

        if (n4 == 512) {
            // Specialized path (N = 2048): 16 LDG.128 front-batched per group,
            // x/y interleaved so the two row-streams advance together.
            #pragma unroll
            for (int g = 0; g < 2; g++) {
                float4 v[16];   // x in v[0,2,4,..], y in v[1,3,5,..]
                #pragma unroll
                for (int u = 0; u < 8; u++) {
                    v[2*u]   = ldcs4(&px[lane + (g * 8 + u) * 32]);
                    v[2*u+1] = ldcs4(&py[lane + (g * 8 + u) * 32]);
                }
                #pragma unroll
                for (int u = 0; u < 8; u++) {
                    float4 x4 = v[2*u], y4 = v[2*u+1];
                    Sx  += (x4.x + x4.y) + (x4.z + x4.w);
                    Sy  += (y4.x + y4.y) + (y4.z + y4.w);
                    Sxx += x4.x*x4.x + x4.y*x4.y + x4.z*x4.z + x4.w*x4.w;
                    Syy += y4.x*y4.x + y4.y*y4.y + y4.z*y4.z + y4.w*y4.w;
                    Sxy += x4.x*y4.x + x4.y*y4.y + x4.z*y4.z + x4.w*y4.w;
                }
            }
            // xd phase: 48 lane-strided iterations = 3 groups of 16 loads.
            #pragma unroll
            for (int g = 0; g < 3; g++) {
                float4 ds[16];
                #pragma unroll
                for (int u = 0; u < 16; u++)
                    ds[u] = ldcs4(&pdl[lane + (g * 16 + u) * 32]);
                #pragma unroll
                for (int u = 0; u < 16; u++) {
                    float4 d = ds[u];
                    Sq += (d.x*d.x + d.y*d.y) + (d.z*d.z + d.w*d.w);
                }
            }
        } else {
            #pragma unroll 4
            for (int j = lane; j < n4; j += 32) {
                float4 x4 = ldcs4(&px[j]);
                float4 y4 = ldcs4(&py[j]);
                Sx  += (x4.x + x4.y) + (x4.z + x4.w);
                Sy  += (y4.x + y4.y) + (y4.z + y4.w);
                Sxx += x4.x*x4.x + x4.y*x4.y + x4.z*x4.z + x4.w*x4.w;
                Syy += y4.x*y4.x + y4.y*y4.y + y4.z*y4.z + y4.w*y4.w;
                Sxy += x4.x*y4.x + x4.y*y4.y + x4.z*y4.z + x4.w*y4.w;
            }
            const int m4 = 3 * n4;
            #pragma unroll 8
            for (int j = lane; j < m4; j += 32) {
                float4 d = ldcs4(&pdl[j]);
                Sq += (d.x*d.x + d.y*d.y) + (d.z*d.z + d.w*d.w);
            }
        }

        // Warp-only reduction of the 6 accumulators.
        const unsigned full = 0xffffffffu;
        #pragma unroll
        for (int off = 16; off > 0; off >>= 1) {
            Sx  += __shfl_down_sync(full, Sx,  off);
            Sy  += __shfl_down_sync(full, Sy,  off);
            Sxx += __shfl_down_sync(full, Sxx, off);
            Syy += __shfl_down_sync(full, Syy, off);
            Sxy += __shfl_down_sync(full, Sxy, off);
            Sq  += __shfl_down_sync(full, Sq,  off);
        }

        if (lane == 0) {
            // ---- scalar (label) math for this batch ----
            const float cx = center[b*3+0], cy = center[b*3+1], cz = center[b*3+2];

            float m0 = mask_mean[b*3+0] - cx;
            float m1 = mask_mean[b*3+1] - cy;
            float m2 = mask_mean[b*3+2] - cz;
            float cdist = sqrtf(m0*m0 + m1*m1 + m2*m2);

            const int sc = size_cls[b];
            float l = mean_sizes[sc*3+0] + size_res[b*3+0];
            float w = mean_sizes[sc*3+1] + size_res[b*3+1];

            const float PI_OVER_12 = 0.26179938779914943654f; // pi/12
            float heading = head_res[b] + (float)head_cls[b] * PI_OVER_12;
            float ch = cosf(heading), sh = sinf(heading);

            float hl = 0.5f * l, hw = 0.5f * w;

            float vn = sqrtf(cx*cx + cy*cy);
            float inv_vn = 1.0f / vn;
            float p0 = -cy * inv_vn, p1 = cx * inv_vn;   // perpendicular dir
            float a0 =  cx * inv_vn, a1 = cy * inv_vn;   // v / |v|

            const float sxA[4] = {1.f, 1.f, -1.f, -1.f};
            const float syA[4] = {1.f, -1.f, -1.f, 1.f};
            float ppmax = -INFINITY, ppmin = INFINITY;
            float prmax = -INFINITY, prmin = INFINITY;
            #pragma unroll
            for (int k = 0; k < 4; k++) {
                float X = ch * hl * sxA[k] - sh * hw * syA[k] + cx;
                float Y = sh * hl * sxA[k] + ch * hw * syA[k] + cy;
                float pp = X * p0 + Y * p1;
                float pr = X * a0 + Y * a1;
                ppmax = fmaxf(ppmax, pp); ppmin = fminf(ppmin, pp);
                prmax = fmaxf(prmax, pr); prmin = fminf(prmin, pr);
            }
            float std_y_label  = (ppmax - ppmin) * 0.25f;
            float mean_y_label = (ppmax + ppmin) * 0.5f;
            float std_label    = (prmax - prmin) * 0.25f;
            float mean_label   = (prmax + prmin) * 0.5f;

            const float Nf = (float)Npts;
            const float invN = 1.0f / Nf;
            const float invNm1 = 1.0f / (Nf - 1.0f);

            float mean_pp = (p0 * Sx + p1 * Sy) * invN;
            float ss_pp   = p0*p0*Sxx + 2.f*p0*p1*Sxy + p1*p1*Syy;
            float var_pp  = (ss_pp - Nf * mean_pp * mean_pp) * invNm1;
            float std_pp  = sqrtf(fmaxf(var_pp, 0.f));

            float mean_pr = (a0 * Sx + a1 * Sy) * invN;
            float ss_pr   = a0*a0*Sxx + 2.f*a0*a1*Sxy + a1*a1*Syy;
            float var_pr  = (ss_pr - Nf * mean_pr * mean_pr) * invNm1;
            float std_pr  = sqrtf(fmaxf(var_pr, 0.f));

            float dnorm = sqrtf(Sq);

            float tval =
                  0.5f  * huber1(cdist)
                + huber1(std_label  - std_pr)
                + huber1(mean_label - mean_pr)
                + 0.01f * huber1(dnorm)
                + huber1(mean_y_label - mean_pp)
                + huber1(std_y_label  - std_pp);

            g_partial[b] = tval;
        }
        // no __syncwarp needed: shuffle sync already converged the warp
    }

    // Block completion counting (single barrier at the very end).
    __shared__ bool s_is_last;
    __syncthreads();
    if (t == 0) {
        __threadfence();
        unsigned prev = atomicAdd(&g_count, 1u);
        s_is_last = (prev == (unsigned)(nblocks - 1));
    }
    __syncthreads();

    // Last-arriving block performs the deterministic final sum (fixed order).
    if (s_is_last) {
        __shared__ float sh[THREADS];
        float s = 0.f;
        for (int i = t; i < Bn; i += THREADS)
            s += g_partial[i];
        sh[t] = s;
        __syncthreads();
        #pragma unroll
        for (int off = THREADS / 2; off > 0; off >>= 1) {
            if (t < off) sh[t] += sh[t + off];
            __syncthreads();
        }
        if (t == 0) {
            out[0] = 0.4f * sh[0] / (float)Bn;
            g_count = 0;   // reset for next graph replay
        }
    }
}

extern "C" void kernel_launch(void* const* d_in, const int* in_sizes, int n_in,
                              void* d_out, int out_size)
{
    const float* mask_mean  = (const float*)d_in[0];  // (B,3)
    const float* pc         = (const float*)d_in[1];  // (B,3,N)
    const float* xd         = (const float*)d_in[2];  // (B,3,N)
    const float* center     = (const float*)d_in[3];  // (B,3)
    const float* size_res   = (const float*)d_in[4];  // (B,3)
    const float* head_res   = (const float*)d_in[5];  // (B,)
    const float* mean_sizes = (const float*)d_in[6];  // (8,3)
    const int*   size_cls   = (const int*)d_in[7];    // (B,)
    const int*   head_cls   = (const int*)d_in[8];    // (B,)

    const int Bn   = in_sizes[0] / 3;
    const int Npts = in_sizes[1] / (3 * Bn);

    // One warp per batch; 4-warp blocks -> 1024 blocks for B=4096.
    int nblocks = (Bn + WARPS_PER_BLOCK - 1) / WARPS_PER_BLOCK;

    loss_warp_kernel<<<nblocks, THREADS>>>(mask_mean, pc, xd, center,
                                           size_res, head_res, mean_sizes,
                                           size_cls, head_cls,
                                           (float*)d_out, Npts, Bn, nblocks);
}

// round 14
// speedup vs baseline: 1.0292x; 1.0292x over previous
#include <cuda_runtime.h>
#include <math.h>

#define THREADS 128
#define WARPS_PER_BLOCK (THREADS / 32)

// Per-batch partial loss scratch (B = 4096 for this problem; padded for safety).
__device__ float g_partial[8192];
__device__ unsigned int g_count;   // zero at module load; reset by last block each call

__device__ __forceinline__ float huber1(float x) {
    float a = fabsf(x);
    float q = fminf(a, 1.0f);
    return 0.5f * q * q + (a - q);
}

__device__ __forceinline__ float4 ld4(const float4* p) {
    return __ldg(p);   // default caching (read-only path); A/B vs __ldcs
}

__global__ __launch_bounds__(THREADS)
void loss_warp_kernel(
    const float* __restrict__ mask_mean,     // (B,3)
    const float* __restrict__ pc,            // (B,3,N)
    const float* __restrict__ xd,            // (B,3,N)
    const float* __restrict__ center,        // (B,3)
    const float* __restrict__ size_res,      // (B,3)
    const float* __restrict__ head_res,      // (B,)
    const float* __restrict__ mean_sizes,    // (8,3)
    const int*   __restrict__ size_cls,      // (B,)
    const int*   __restrict__ head_cls,      // (B,)
    float* __restrict__ out,
    int Npts, int Bn, int nblocks)
{
    const int t    = threadIdx.x;
    const int lane = t & 31;
    const int wid  = t >> 5;
    const int gw   = blockIdx.x * WARPS_PER_BLOCK + wid;   // global warp id
    const int nwarps = nblocks * WARPS_PER_BLOCK;
    const int n4 = Npts >> 2;          // float4s per row

    // Each warp processes whole batches independently — no block barriers
    // anywhere in the streaming path.
    for (int b = gw; b < Bn; b += nwarps) {
        const size_t base = (size_t)b * 3 * (size_t)Npts;
        const float4* __restrict__ px  = (const float4*)(pc + base);           // x row
        const float4* __restrict__ py  = (const float4*)(pc + base + Npts);    // y row
        const float4* __restrict__ pdl = (const float4*)(xd + base);           // all 3 rows

        float Sx = 0.f, Sy = 0.f, Sxx = 0.f, Syy = 0.f, Sxy = 0.f, Sq = 0.f;

        if (n4 == 512) {
            // Specialized path (N = 2048): front-batched load groups.
            #pragma unroll
            for (int g = 0; g < 2; g++) {
                float4 xs[8], ys[8];
                #pragma unroll
                for (int u = 0; u < 8; u++)
                    xs[u] = ld4(&px[lane + (g * 8 + u) * 32]);
                #pragma unroll
                for (int u = 0; u < 8; u++)
                    ys[u] = ld4(&py[lane + (g * 8 + u) * 32]);
                #pragma unroll
                for (int u = 0; u < 8; u++) {
                    float4 x4 = xs[u], y4 = ys[u];
                    Sx  += (x4.x + x4.y) + (x4.z + x4.w);
                    Sy  += (y4.x + y4.y) + (y4.z + y4.w);
                    Sxx += x4.x*x4.x + x4.y*x4.y + x4.z*x4.z + x4.w*x4.w;
                    Syy += y4.x*y4.x + y4.y*y4.y + y4.z*y4.z + y4.w*y4.w;
                    Sxy += x4.x*y4.x + x4.y*y4.y + x4.z*y4.z + x4.w*y4.w;
                }
            }
            // xd phase: 48 lane-strided iterations = 3 groups of 16 loads.
            #pragma unroll
            for (int g = 0; g < 3; g++) {
                float4 ds[16];
                #pragma unroll
                for (int u = 0; u < 16; u++)
                    ds[u] = ld4(&pdl[lane + (g * 16 + u) * 32]);
                #pragma unroll
                for (int u = 0; u < 16; u++) {
                    float4 d = ds[u];
                    Sq += (d.x*d.x + d.y*d.y) + (d.z*d.z + d.w*d.w);
                }
            }
        } else {
            #pragma unroll 4
            for (int j = lane; j < n4; j += 32) {
                float4 x4 = ld4(&px[j]);
                float4 y4 = ld4(&py[j]);
                Sx  += (x4.x + x4.y) + (x4.z + x4.w);
                Sy  += (y4.x + y4.y) + (y4.z + y4.w);
                Sxx += x4.x*x4.x + x4.y*x4.y + x4.z*x4.z + x4.w*x4.w;
                Syy += y4.x*y4.x + y4.y*y4.y + y4.z*y4.z + y4.w*y4.w;
                Sxy += x4.x*y4.x + x4.y*y4.y + x4.z*y4.z + x4.w*y4.w;
            }
            const int m4 = 3 * n4;
            #pragma unroll 8
            for (int j = lane; j < m4; j += 32) {
                float4 d = ld4(&pdl[j]);
                Sq += (d.x*d.x + d.y*d.y) + (d.z*d.z + d.w*d.w);
            }
        }

        // Warp-only reduction of the 6 accumulators.
        const unsigned full = 0xffffffffu;
        #pragma unroll
        for (int off = 16; off > 0; off >>= 1) {
            Sx  += __shfl_down_sync(full, Sx,  off);
            Sy  += __shfl_down_sync(full, Sy,  off);
            Sxx += __shfl_down_sync(full, Sxx, off);
            Syy += __shfl_down_sync(full, Syy, off);
            Sxy += __shfl_down_sync(full, Sxy, off);
            Sq  += __shfl_down_sync(full, Sq,  off);
        }

        if (lane == 0) {
            // ---- scalar (label) math for this batch ----
            const float cx = center[b*3+0], cy = center[b*3+1], cz = center[b*3+2];

            float m0 = mask_mean[b*3+0] - cx;
            float m1 = mask_mean[b*3+1] - cy;
            float m2 = mask_mean[b*3+2] - cz;
            float cdist = sqrtf(m0*m0 + m1*m1 + m2*m2);

            const int sc = size_cls[b];
            float l = mean_sizes[sc*3+0] + size_res[b*3+0];
            float w = mean_sizes[sc*3+1] + size_res[b*3+1];

            const float PI_OVER_12 = 0.26179938779914943654f; // pi/12
            float heading = head_res[b] + (float)head_cls[b] * PI_OVER_12;
            float ch = cosf(heading), sh = sinf(heading);

            float hl = 0.5f * l, hw = 0.5f * w;

            float vn = sqrtf(cx*cx + cy*cy);
            float inv_vn = 1.0f / vn;
            float p0 = -cy * inv_vn, p1 = cx * inv_vn;   // perpendicular dir
            float a0 =  cx * inv_vn, a1 = cy * inv_vn;   // v / |v|

            const float sxA[4] = {1.f, 1.f, -1.f, -1.f};
            const float syA[4] = {1.f, -1.f, -1.f, 1.f};
            float ppmax = -INFINITY, ppmin = INFINITY;
            float prmax = -INFINITY, prmin = INFINITY;
            #pragma unroll
            for (int k = 0; k < 4; k++) {
                float X = ch * hl * sxA[k] - sh * hw * syA[k] + cx;
                float Y = sh * hl * sxA[k] + ch * hw * syA[k] + cy;
                float pp = X * p0 + Y * p1;
                float pr = X * a0 + Y * a1;
                ppmax = fmaxf(ppmax, pp); ppmin = fminf(ppmin, pp);
                prmax = fmaxf(prmax, pr); prmin = fminf(prmin, pr);
            }
            float std_y_label  = (ppmax - ppmin) * 0.25f;
            float mean_y_label = (ppmax + ppmin) * 0.5f;
            float std_label    = (prmax - prmin) * 0.25f;
            float mean_label   = (prmax + prmin) * 0.5f;

            const float Nf = (float)Npts;
            const float invN = 1.0f / Nf;
            const float invNm1 = 1.0f / (Nf - 1.0f);

            float mean_pp = (p0 * Sx + p1 * Sy) * invN;
            float ss_pp   = p0*p0*Sxx + 2.f*p0*p1*Sxy + p1*p1*Syy;
            float var_pp  = (ss_pp - Nf * mean_pp * mean_pp) * invNm1;
            float std_pp  = sqrtf(fmaxf(var_pp, 0.f));

            float mean_pr = (a0 * Sx + a1 * Sy) * invN;
            float ss_pr   = a0*a0*Sxx + 2.f*a0*a1*Sxy + a1*a1*Syy;
            float var_pr  = (ss_pr - Nf * mean_pr * mean_pr) * invNm1;
            float std_pr  = sqrtf(fmaxf(var_pr, 0.f));

            float dnorm = sqrtf(Sq);

            float tval =
                  0.5f  * huber1(cdist)
                + huber1(std_label  - std_pr)
                + huber1(mean_label - mean_pr)
                + 0.01f * huber1(dnorm)
                + huber1(mean_y_label - mean_pp)
                + huber1(std_y_label  - std_pp);

            g_partial[b] = tval;
        }
        // no __syncwarp needed: shuffle sync already converged the warp
    }

    // Block completion counting (single barrier at the very end).
    __shared__ bool s_is_last;
    __syncthreads();
    if (t == 0) {
        __threadfence();
        unsigned prev = atomicAdd(&g_count, 1u);
        s_is_last = (prev == (unsigned)(nblocks - 1));
    }
    __syncthreads();

    // Last-arriving block performs the deterministic final sum (fixed order).
    if (s_is_last) {
        __shared__ float sh[THREADS];
        float s = 0.f;
        for (int i = t; i < Bn; i += THREADS)
            s += g_partial[i];
        sh[t] = s;
        __syncthreads();
        #pragma unroll
        for (int off = THREADS / 2; off > 0; off >>= 1) {
            if (t < off) sh[t] += sh[t + off];
            __syncthreads();
        }
        if (t == 0) {
            out[0] = 0.4f * sh[0] / (float)Bn;
            g_count = 0;   // reset for next graph replay
        }
    }
}

extern "C" void kernel_launch(void* const* d_in, const int* in_sizes, int n_in,
                              void* d_out, int out_size)
{
    const float* mask_mean  = (const float*)d_in[0];  // (B,3)
    const float* pc         = (const float*)d_in[1];  // (B,3,N)
    const float* xd         = (const float*)d_in[2];  // (B,3,N)
    const float* center     = (const float*)d_in[3];  // (B,3)
    const float* size_res   = (const float*)d_in[4];  // (B,3)
    const float* head_res   = (const float*)d_in[5];  // (B,)
    const float* mean_sizes = (const float*)d_in[6];  // (8,3)
    const int*   size_cls   = (const int*)d_in[7];    // (B,)
    const int*   head_cls   = (const int*)d_in[8];    // (B,)

    const int Bn   = in_sizes[0] / 3;
    const int Npts = in_sizes[1] / (3 * Bn);

    // One warp per batch; 4-warp blocks -> 1024 blocks for B=4096.
    int nblocks = (Bn + WARPS_PER_BLOCK - 1) / WARPS_PER_BLOCK;

    loss_warp_kernel<<<nblocks, THREADS>>>(mask_mean, pc, xd, center,
                                           size_res, head_res, mean_sizes,
                                           size_cls, head_cls,
                                           (float*)d_out, Npts, Bn, nblocks);
}